// round 7
// baseline (speedup 1.0000x reference)
#include <cuda_runtime.h>
#include <cuda_bf16.h>
#include <cstdint>

// ============================================================================
// Problem constants
// ============================================================================
#define IN_F   1024
#define OUT_F  1024
#define INT_DIM 128
#define M_ROWS 16384              // 8 * 2048
#define WN (OUT_F * IN_F)         // 1048576
#define XN (M_ROWS * IN_F)        // 16777216

// Device-global scratch (allocation-free rule: __device__ globals are allowed)
__device__ __nv_bfloat16 g_W_hi[WN];   // W split high half, [OUT_F][IN_F] K-major
__device__ __nv_bfloat16 g_W_lo[WN];   // W split low  half
__device__ __nv_bfloat16 g_x_hi[XN];   // x split high half, [M_ROWS][IN_F]
__device__ __nv_bfloat16 g_x_lo[XN];   // x split low  half
__device__ float         g_bias[OUT_F];

__device__ __forceinline__ uint32_t smem_u32(const void* p) {
    uint32_t a;
    asm("{ .reg .u64 t; cvta.to.shared.u64 t, %1; cvt.u32.u64 %0, t; }"
        : "=r"(a) : "l"(p));
    return a;
}

__device__ __forceinline__ unsigned pack2(__nv_bfloat16 a, __nv_bfloat16 b) {
    return (unsigned)__bfloat16_as_ushort(a) | ((unsigned)__bfloat16_as_ushort(b) << 16);
}

// split a float4 into bf16 hi / lo packed uint2's
__device__ __forceinline__ void split4(float4 v, uint2& hi, uint2& lo) {
    __nv_bfloat16 h0 = __float2bfloat16(v.x), h1 = __float2bfloat16(v.y);
    __nv_bfloat16 h2 = __float2bfloat16(v.z), h3 = __float2bfloat16(v.w);
    __nv_bfloat16 l0 = __float2bfloat16(v.x - __bfloat162float(h0));
    __nv_bfloat16 l1 = __float2bfloat16(v.y - __bfloat162float(h1));
    __nv_bfloat16 l2 = __float2bfloat16(v.z - __bfloat162float(h2));
    __nv_bfloat16 l3 = __float2bfloat16(v.w - __bfloat162float(h3));
    hi = make_uint2(pack2(h0, h1), pack2(h2, h3));
    lo = make_uint2(pack2(l0, l1), pack2(l2, l3));
}

// ============================================================================
// Stage 1 (fused prep): one kernel, blockIdx-partitioned.
//   blocks [0, 16384)          : split x  -> g_x_hi / g_x_lo   (64MB rd, 64MB wr)
//   blocks [16384, 17408)      : W = coef @ P_w, split bf16    (512MB rd, 4MB wr)
//   blocks [17408, 17412)      : bias = bias_coef @ P_b
// All streaming, DRAM bound (~650 MB -> ~110 us measured, near HBM ceiling).
// ============================================================================
#define XB (XN / (256 * 4))        // 16384 blocks for x split
#define WB (WN / (256 * 4))        // 1024 blocks for W materialize

__global__ void __launch_bounds__(256)
prep_kernel(const float* __restrict__ x,  const float* __restrict__ wc,
            const float* __restrict__ bc, const float* __restrict__ Pw,
            const float* __restrict__ Pb) {
    int bx = blockIdx.x;
    int tid = threadIdx.x;

    if (bx < XB) {
        // ---- split x into bf16 hi/lo ----
        size_t pos = ((size_t)bx * 256 + tid) * 4;
        float4 v = *reinterpret_cast<const float4*>(x + pos);
        uint2 hi, lo;
        split4(v, hi, lo);
        *reinterpret_cast<uint2*>(g_x_hi + pos) = hi;
        *reinterpret_cast<uint2*>(g_x_lo + pos) = lo;
    } else if (bx < XB + WB) {
        // ---- materialize W ----
        __shared__ float c[INT_DIM];
        if (tid < INT_DIM) c[tid] = wc[tid];
        __syncthreads();
        size_t pos = ((size_t)(bx - XB) * 256 + tid) * 4;
        float4 acc = make_float4(0.f, 0.f, 0.f, 0.f);
#pragma unroll 8
        for (int d = 0; d < INT_DIM; d++) {
            float4 p = *reinterpret_cast<const float4*>(Pw + (size_t)d * WN + pos);
            float cd = c[d];
            acc.x = fmaf(cd, p.x, acc.x);
            acc.y = fmaf(cd, p.y, acc.y);
            acc.z = fmaf(cd, p.z, acc.z);
            acc.w = fmaf(cd, p.w, acc.w);
        }
        uint2 hi, lo;
        split4(acc, hi, lo);
        *reinterpret_cast<uint2*>(g_W_hi + pos) = hi;
        *reinterpret_cast<uint2*>(g_W_lo + pos) = lo;
    } else {
        // ---- materialize bias ----
        __shared__ float c[INT_DIM];
        if (tid < INT_DIM) c[tid] = bc[tid];
        __syncthreads();
        int o = (bx - XB - WB) * 256 + tid;
        float acc = 0.f;
#pragma unroll 8
        for (int d = 0; d < INT_DIM; d++)
            acc = fmaf(c[d], Pb[(size_t)d * OUT_F + o], acc);
        g_bias[o] = acc;
    }
}

// ============================================================================
// Stage 2: split-bf16 GEMM via mma.sync.m16n8k16.
//   acc += xhi*Whi + xhi*Wlo + xlo*Whi   (lo*lo dropped, ~5e-6 rel)
//
// CTA tile 128(M) x 256(N), K-chunk 64, double-buffered:
//   stage = [A_hi 16K | A_lo 16K | B_hi 32K | B_lo 32K] = 96 KB, x2 = 192 KB
// 8 warps: 2(M) x 4(N), warp tile 64 x 64 -> smem bytes per MMA 1.5x lower
// than the previous 64x32 warp tile (crossbar was co-bottleneck at 71%).
// 16B chunk ch of row r stored at ch ^ (r & 7) -> conflict-free ldmatrix.
// ============================================================================
#define SM_STAGE 98304
#define OFF_A_HI 0
#define OFF_A_LO 16384
#define OFF_B_HI 32768
#define OFF_B_LO 65536
#define GEMM_SMEM (2 * SM_STAGE)
#define NKC 16   // 1024 / 64

__device__ __forceinline__ void ldsm_x4(uint32_t* r, uint32_t addr) {
    asm volatile("ldmatrix.sync.aligned.m8n8.x4.shared.b16 {%0,%1,%2,%3}, [%4];"
                 : "=r"(r[0]), "=r"(r[1]), "=r"(r[2]), "=r"(r[3]) : "r"(addr));
}
__device__ __forceinline__ void mma16816(float* d, const uint32_t* a, const uint32_t* b) {
    asm volatile(
        "mma.sync.aligned.m16n8k16.row.col.f32.bf16.bf16.f32 "
        "{%0,%1,%2,%3}, {%4,%5,%6,%7}, {%8,%9}, {%0,%1,%2,%3};"
        : "+f"(d[0]), "+f"(d[1]), "+f"(d[2]), "+f"(d[3])
        : "r"(a[0]), "r"(a[1]), "r"(a[2]), "r"(a[3]), "r"(b[0]), "r"(b[1]));
}
__device__ __forceinline__ void cp_async16(uint32_t dst, const void* src) {
    asm volatile("cp.async.cg.shared.global [%0], [%1], 16;"
                 :: "r"(dst), "l"(src) : "memory");
}
#define CP_COMMIT() asm volatile("cp.async.commit_group;" ::: "memory")
#define CP_WAIT0()  asm volatile("cp.async.wait_group 0;" ::: "memory")

// swizzled byte offset inside one [rows x 128B] tile
__device__ __forceinline__ uint32_t sw_off(int row, int ch16) {
    return (uint32_t)(row * 128 + ((ch16 ^ (row & 7)) << 4));
}

__global__ void __launch_bounds__(256, 1)
gemm_kernel(float* __restrict__ out) {
    extern __shared__ char smem[];
    uint32_t sb = smem_u32(smem);
    int tid  = threadIdx.x;
    int wid  = tid >> 5;
    int lane = tid & 31;
    int wm   = wid >> 2;          // 0..1, 64-row half of M128
    int wn   = wid & 3;           // 0..3, 64-col quarter of N256
    // Consecutive blocks share the same x m-tile -> L2 reuse of x.
    int m0 = (int)(blockIdx.x >> 2) * 128;
    int n0 = (int)(blockIdx.x & 3) * 256;

    const __nv_bfloat16* ahp = g_x_hi + (size_t)m0 * IN_F;
    const __nv_bfloat16* alp = g_x_lo + (size_t)m0 * IN_F;
    const __nv_bfloat16* bhp = g_W_hi + (size_t)n0 * IN_F;
    const __nv_bfloat16* blp = g_W_lo + (size_t)n0 * IN_F;

    // cp.async geometry:
    // A halves: 128 rows x 8 ch = 1024 slots, 4 per thread
    // B halves: 256 rows x 8 ch = 2048 slots, 8 per thread
    int ar[4], ach[4];
#pragma unroll
    for (int j = 0; j < 4; ++j) { int e = tid + j * 256; ar[j] = e >> 3; ach[j] = e & 7; }
    int br[8], bch[8];
#pragma unroll
    for (int j = 0; j < 8; ++j) { int e = tid + j * 256; br[j] = e >> 3; bch[j] = e & 7; }

    float acc[4][8][4];
#pragma unroll
    for (int mi = 0; mi < 4; ++mi)
#pragma unroll
        for (int ni = 0; ni < 8; ++ni)
#pragma unroll
            for (int q = 0; q < 4; ++q) acc[mi][ni][q] = 0.f;

    // ---- prologue: fill buffer 0 with chunk 0 ----
#pragma unroll
    for (int j = 0; j < 4; ++j) {
        uint32_t d = sw_off(ar[j], ach[j]);
        size_t g = (size_t)ar[j] * IN_F + ach[j] * 8;
        cp_async16(sb + OFF_A_HI + d, ahp + g);
        cp_async16(sb + OFF_A_LO + d, alp + g);
    }
#pragma unroll
    for (int j = 0; j < 8; ++j) {
        uint32_t d = sw_off(br[j], bch[j]);
        size_t g = (size_t)br[j] * IN_F + bch[j] * 8;
        cp_async16(sb + OFF_B_HI + d, bhp + g);
        cp_async16(sb + OFF_B_LO + d, blp + g);
    }
    CP_COMMIT();
    CP_WAIT0();
    __syncthreads();

    // ---- main loop over 16 K-chunks, double-buffered ----
    for (int c = 0; c < NKC; ++c) {
        uint32_t buf  = (uint32_t)(c & 1) * SM_STAGE;
        uint32_t nbuf = buf ^ SM_STAGE;
        bool pf = (c + 1 < NKC);

        if (pf) {
            int k1 = (c + 1) * 64;
#pragma unroll
            for (int j = 0; j < 4; ++j) {
                uint32_t d = sw_off(ar[j], ach[j]);
                size_t g = (size_t)ar[j] * IN_F + k1 + ach[j] * 8;
                cp_async16(sb + nbuf + OFF_A_HI + d, ahp + g);
                cp_async16(sb + nbuf + OFF_A_LO + d, alp + g);
            }
#pragma unroll
            for (int j = 0; j < 8; ++j) {
                uint32_t d = sw_off(br[j], bch[j]);
                size_t g = (size_t)br[j] * IN_F + k1 + bch[j] * 8;
                cp_async16(sb + nbuf + OFF_B_HI + d, bhp + g);
                cp_async16(sb + nbuf + OFF_B_LO + d, blp + g);
            }
            CP_COMMIT();
        }

        // ---- compute on buf: 4 k16 steps ----
#pragma unroll
        for (int ks = 0; ks < 4; ++ks) {
            // B fragments: 4 n16 groups per half, ldmatrix.x4 each
            uint32_t bhi[4][4], blo[4][4];
#pragma unroll
            for (int ng = 0; ng < 4; ++ng) {
                int nrow = wn * 64 + ng * 16 + ((lane >> 4) << 3) + (lane & 7);
                int ch   = ks * 2 + ((lane >> 3) & 1);
                uint32_t a = sb + buf + sw_off(nrow, ch);
                ldsm_x4(bhi[ng], a + OFF_B_HI);
                ldsm_x4(blo[ng], a + OFF_B_LO);
            }
            // A fragments: 4 m16 groups per half
            uint32_t ahi[4][4], alo[4][4];
#pragma unroll
            for (int mi = 0; mi < 4; ++mi) {
                int mrow = wm * 64 + mi * 16 + (lane & 15);
                int ch   = ks * 2 + (lane >> 4);
                uint32_t a = sb + buf + sw_off(mrow, ch);
                ldsm_x4(ahi[mi], a + OFF_A_HI);
                ldsm_x4(alo[mi], a + OFF_A_LO);
            }
            // 96 MMAs, grouped by term so same-acc RAW chains are 32 apart
#pragma unroll
            for (int mi = 0; mi < 4; ++mi)
#pragma unroll
                for (int ni = 0; ni < 8; ++ni)
                    mma16816(acc[mi][ni], ahi[mi], &bhi[ni >> 1][(ni & 1) * 2]);
#pragma unroll
            for (int mi = 0; mi < 4; ++mi)
#pragma unroll
                for (int ni = 0; ni < 8; ++ni)
                    mma16816(acc[mi][ni], ahi[mi], &blo[ni >> 1][(ni & 1) * 2]);
#pragma unroll
            for (int mi = 0; mi < 4; ++mi)
#pragma unroll
                for (int ni = 0; ni < 8; ++ni)
                    mma16816(acc[mi][ni], alo[mi], &bhi[ni >> 1][(ni & 1) * 2]);
        }

        if (pf) {
            CP_WAIT0();
            __syncthreads();
        }
    }

    // ---- epilogue: acc -> global with bias ----
#pragma unroll
    for (int ni = 0; ni < 8; ++ni) {
        int col = n0 + wn * 64 + ni * 8 + ((lane & 3) << 1);
        float b0 = g_bias[col];
        float b1 = g_bias[col + 1];
#pragma unroll
        for (int mi = 0; mi < 4; ++mi) {
            int row0 = m0 + wm * 64 + mi * 16 + (lane >> 2);
            float2 v0 = make_float2(acc[mi][ni][0] + b0, acc[mi][ni][1] + b1);
            float2 v1 = make_float2(acc[mi][ni][2] + b0, acc[mi][ni][3] + b1);
            *reinterpret_cast<float2*>(out + (size_t)row0 * OUT_F + col) = v0;
            *reinterpret_cast<float2*>(out + (size_t)(row0 + 8) * OUT_F + col) = v1;
        }
    }
}

// ============================================================================
// kernel_launch: 2 graph-capturable kernel launches, no sync, no alloc.
// Inputs (metadata order): x, weight_coef, bias_coef, P_w, P_b. Output fp32.
// ============================================================================
extern "C" void kernel_launch(void* const* d_in, const int* in_sizes, int n_in,
                              void* d_out, int out_size) {
    const float* x  = (const float*)d_in[0];
    const float* wc = (const float*)d_in[1];
    const float* bc = (const float*)d_in[2];
    const float* Pw = (const float*)d_in[3];
    const float* Pb = (const float*)d_in[4];
    float* out = (float*)d_out;

    (void)in_sizes; (void)n_in; (void)out_size;

    cudaFuncSetAttribute(gemm_kernel,
                         cudaFuncAttributeMaxDynamicSharedMemorySize, GEMM_SMEM);

    // Stage 1: fused prep (x split + W materialize + bias), DRAM bound ~650MB
    prep_kernel<<<XB + WB + OUT_F / 256, 256>>>(x, wc, bc, Pw, Pb);

    // Stage 2: y = x @ W^T + b via split-bf16 mma.sync (3 MMAs per k16 step)
    // Grid: 128 M-tiles x 4 N-tiles; same-m-tile blocks adjacent for x L2 reuse.
    gemm_kernel<<<(M_ROWS / 128) * (OUT_F / 256), 256, GEMM_SMEM>>>(out);
}

// round 8
// speedup vs baseline: 1.0140x; 1.0140x over previous
#include <cuda_runtime.h>
#include <cuda_bf16.h>
#include <cstdint>

// ============================================================================
// Problem constants
// ============================================================================
#define IN_F   1024
#define OUT_F  1024
#define INT_DIM 128
#define M_ROWS 16384              // 8 * 2048
#define WN (OUT_F * IN_F)         // 1048576
#define XN (M_ROWS * IN_F)        // 16777216

// Device-global scratch (allocation-free rule: __device__ globals are allowed)
__device__ __nv_bfloat16 g_W_hi[WN];   // W split high half, [OUT_F][IN_F] K-major
__device__ __nv_bfloat16 g_W_lo[WN];   // W split low  half
__device__ __nv_bfloat16 g_x_hi[XN];   // x split high half, [M_ROWS][IN_F]
__device__ __nv_bfloat16 g_x_lo[XN];   // x split low  half
__device__ float         g_bias[OUT_F];

__device__ __forceinline__ uint32_t smem_u32(const void* p) {
    uint32_t a;
    asm("{ .reg .u64 t; cvta.to.shared.u64 t, %1; cvt.u32.u64 %0, t; }"
        : "=r"(a) : "l"(p));
    return a;
}

__device__ __forceinline__ unsigned pack2(__nv_bfloat16 a, __nv_bfloat16 b) {
    return (unsigned)__bfloat16_as_ushort(a) | ((unsigned)__bfloat16_as_ushort(b) << 16);
}

// split a float4 into bf16 hi / lo packed uint2's
__device__ __forceinline__ void split4(float4 v, uint2& hi, uint2& lo) {
    __nv_bfloat16 h0 = __float2bfloat16(v.x), h1 = __float2bfloat16(v.y);
    __nv_bfloat16 h2 = __float2bfloat16(v.z), h3 = __float2bfloat16(v.w);
    __nv_bfloat16 l0 = __float2bfloat16(v.x - __bfloat162float(h0));
    __nv_bfloat16 l1 = __float2bfloat16(v.y - __bfloat162float(h1));
    __nv_bfloat16 l2 = __float2bfloat16(v.z - __bfloat162float(h2));
    __nv_bfloat16 l3 = __float2bfloat16(v.w - __bfloat162float(h3));
    hi = make_uint2(pack2(h0, h1), pack2(h2, h3));
    lo = make_uint2(pack2(l0, l1), pack2(l2, l3));
}

// ============================================================================
// Stage 1 (fused prep): one kernel, blockIdx-partitioned.
//   blocks [0, 16384)          : split x  -> g_x_hi / g_x_lo   (64MB rd, 64MB wr)
//   blocks [16384, 17408)      : W = coef @ P_w, split bf16    (512MB rd, 4MB wr)
//   blocks [17408, 17412)      : bias = bias_coef @ P_b
// All streaming, DRAM bound (~650 MB -> ~110 us measured, near HBM ceiling).
// ============================================================================
#define XB (XN / (256 * 4))        // 16384 blocks for x split
#define WB (WN / (256 * 4))        // 1024 blocks for W materialize

__global__ void __launch_bounds__(256)
prep_kernel(const float* __restrict__ x,  const float* __restrict__ wc,
            const float* __restrict__ bc, const float* __restrict__ Pw,
            const float* __restrict__ Pb) {
    int bx = blockIdx.x;
    int tid = threadIdx.x;

    if (bx < XB) {
        // ---- split x into bf16 hi/lo ----
        size_t pos = ((size_t)bx * 256 + tid) * 4;
        float4 v = *reinterpret_cast<const float4*>(x + pos);
        uint2 hi, lo;
        split4(v, hi, lo);
        *reinterpret_cast<uint2*>(g_x_hi + pos) = hi;
        *reinterpret_cast<uint2*>(g_x_lo + pos) = lo;
    } else if (bx < XB + WB) {
        // ---- materialize W ----
        __shared__ float c[INT_DIM];
        if (tid < INT_DIM) c[tid] = wc[tid];
        __syncthreads();
        size_t pos = ((size_t)(bx - XB) * 256 + tid) * 4;
        float4 acc = make_float4(0.f, 0.f, 0.f, 0.f);
#pragma unroll 8
        for (int d = 0; d < INT_DIM; d++) {
            float4 p = *reinterpret_cast<const float4*>(Pw + (size_t)d * WN + pos);
            float cd = c[d];
            acc.x = fmaf(cd, p.x, acc.x);
            acc.y = fmaf(cd, p.y, acc.y);
            acc.z = fmaf(cd, p.z, acc.z);
            acc.w = fmaf(cd, p.w, acc.w);
        }
        uint2 hi, lo;
        split4(acc, hi, lo);
        *reinterpret_cast<uint2*>(g_W_hi + pos) = hi;
        *reinterpret_cast<uint2*>(g_W_lo + pos) = lo;
    } else {
        // ---- materialize bias ----
        __shared__ float c[INT_DIM];
        if (tid < INT_DIM) c[tid] = bc[tid];
        __syncthreads();
        int o = (bx - XB - WB) * 256 + tid;
        float acc = 0.f;
#pragma unroll 8
        for (int d = 0; d < INT_DIM; d++)
            acc = fmaf(c[d], Pb[(size_t)d * OUT_F + o], acc);
        g_bias[o] = acc;
    }
}

// ============================================================================
// Stage 2: split-bf16 GEMM via mma.sync.m16n8k16.
//   acc += xhi*Whi + xhi*Wlo + xlo*Whi   (lo*lo dropped, ~5e-6 rel)
//
// CTA tile 128(M) x 256(N), K-chunk 64, double-buffered:
//   stage = [A_hi 16K | A_lo 16K | B_hi 32K | B_lo 32K] = 96 KB, x2 = 192 KB
// 8 warps: 2(M) x 4(N), warp tile 64 x 64 (85 smem B/MMA vs 128 for 64x32).
// Register-liveness fix vs round 7 (which spilled at 255 regs): B fragments
// are loaded and consumed in TWO halves of the 64-wide N range per k16 step,
// capping live regs at acc(128) + A(32) + B(16) + addressing ~= 205.
// 16B chunk ch of row r stored at ch ^ (r & 7) -> conflict-free ldmatrix.
// ============================================================================
#define SM_STAGE 98304
#define OFF_A_HI 0
#define OFF_A_LO 16384
#define OFF_B_HI 32768
#define OFF_B_LO 65536
#define GEMM_SMEM (2 * SM_STAGE)
#define NKC 16   // 1024 / 64

__device__ __forceinline__ void ldsm_x4(uint32_t* r, uint32_t addr) {
    asm volatile("ldmatrix.sync.aligned.m8n8.x4.shared.b16 {%0,%1,%2,%3}, [%4];"
                 : "=r"(r[0]), "=r"(r[1]), "=r"(r[2]), "=r"(r[3]) : "r"(addr));
}
__device__ __forceinline__ void mma16816(float* d, const uint32_t* a, const uint32_t* b) {
    asm volatile(
        "mma.sync.aligned.m16n8k16.row.col.f32.bf16.bf16.f32 "
        "{%0,%1,%2,%3}, {%4,%5,%6,%7}, {%8,%9}, {%0,%1,%2,%3};"
        : "+f"(d[0]), "+f"(d[1]), "+f"(d[2]), "+f"(d[3])
        : "r"(a[0]), "r"(a[1]), "r"(a[2]), "r"(a[3]), "r"(b[0]), "r"(b[1]));
}
__device__ __forceinline__ void cp_async16(uint32_t dst, const void* src) {
    asm volatile("cp.async.cg.shared.global [%0], [%1], 16;"
                 :: "r"(dst), "l"(src) : "memory");
}
#define CP_COMMIT() asm volatile("cp.async.commit_group;" ::: "memory")
#define CP_WAIT0()  asm volatile("cp.async.wait_group 0;" ::: "memory")

// swizzled byte offset inside one [rows x 128B] tile
__device__ __forceinline__ uint32_t sw_off(int row, int ch16) {
    return (uint32_t)(row * 128 + ((ch16 ^ (row & 7)) << 4));
}

__global__ void __launch_bounds__(256, 1)
gemm_kernel(float* __restrict__ out) {
    extern __shared__ char smem[];
    uint32_t sb = smem_u32(smem);
    int tid  = threadIdx.x;
    int wid  = tid >> 5;
    int lane = tid & 31;
    int wm   = wid >> 2;          // 0..1, 64-row half of M128
    int wn   = wid & 3;           // 0..3, 64-col quarter of N256
    // Consecutive blocks share the same x m-tile -> L2 reuse of x.
    int m0 = (int)(blockIdx.x >> 2) * 128;
    int n0 = (int)(blockIdx.x & 3) * 256;

    const __nv_bfloat16* ahp = g_x_hi + (size_t)m0 * IN_F;
    const __nv_bfloat16* alp = g_x_lo + (size_t)m0 * IN_F;
    const __nv_bfloat16* bhp = g_W_hi + (size_t)n0 * IN_F;
    const __nv_bfloat16* blp = g_W_lo + (size_t)n0 * IN_F;

    // cp.async geometry:
    // A halves: 128 rows x 8 ch = 1024 slots, 4 per thread
    // B halves: 256 rows x 8 ch = 2048 slots, 8 per thread
    int ar[4], ach[4];
#pragma unroll
    for (int j = 0; j < 4; ++j) { int e = tid + j * 256; ar[j] = e >> 3; ach[j] = e & 7; }
    int br[8], bch[8];
#pragma unroll
    for (int j = 0; j < 8; ++j) { int e = tid + j * 256; br[j] = e >> 3; bch[j] = e & 7; }

    float acc[4][8][4];
#pragma unroll
    for (int mi = 0; mi < 4; ++mi)
#pragma unroll
        for (int ni = 0; ni < 8; ++ni)
#pragma unroll
            for (int q = 0; q < 4; ++q) acc[mi][ni][q] = 0.f;

    // ---- prologue: fill buffer 0 with chunk 0 ----
#pragma unroll
    for (int j = 0; j < 4; ++j) {
        uint32_t d = sw_off(ar[j], ach[j]);
        size_t g = (size_t)ar[j] * IN_F + ach[j] * 8;
        cp_async16(sb + OFF_A_HI + d, ahp + g);
        cp_async16(sb + OFF_A_LO + d, alp + g);
    }
#pragma unroll
    for (int j = 0; j < 8; ++j) {
        uint32_t d = sw_off(br[j], bch[j]);
        size_t g = (size_t)br[j] * IN_F + bch[j] * 8;
        cp_async16(sb + OFF_B_HI + d, bhp + g);
        cp_async16(sb + OFF_B_LO + d, blp + g);
    }
    CP_COMMIT();
    CP_WAIT0();
    __syncthreads();

    // ---- main loop over 16 K-chunks, double-buffered ----
    for (int c = 0; c < NKC; ++c) {
        uint32_t buf  = (uint32_t)(c & 1) * SM_STAGE;
        uint32_t nbuf = buf ^ SM_STAGE;
        bool pf = (c + 1 < NKC);

        if (pf) {
            int k1 = (c + 1) * 64;
#pragma unroll
            for (int j = 0; j < 4; ++j) {
                uint32_t d = sw_off(ar[j], ach[j]);
                size_t g = (size_t)ar[j] * IN_F + k1 + ach[j] * 8;
                cp_async16(sb + nbuf + OFF_A_HI + d, ahp + g);
                cp_async16(sb + nbuf + OFF_A_LO + d, alp + g);
            }
#pragma unroll
            for (int j = 0; j < 8; ++j) {
                uint32_t d = sw_off(br[j], bch[j]);
                size_t g = (size_t)br[j] * IN_F + k1 + bch[j] * 8;
                cp_async16(sb + nbuf + OFF_B_HI + d, bhp + g);
                cp_async16(sb + nbuf + OFF_B_LO + d, blp + g);
            }
            CP_COMMIT();
        }

        // ---- compute on buf: 4 k16 steps ----
#pragma unroll
        for (int ks = 0; ks < 4; ++ks) {
            // A fragments: 4 m16 groups per half, live across the whole ks
            uint32_t ahi[4][4], alo[4][4];
#pragma unroll
            for (int mi = 0; mi < 4; ++mi) {
                int mrow = wm * 64 + mi * 16 + (lane & 15);
                int ch   = ks * 2 + (lane >> 4);
                uint32_t a = sb + buf + sw_off(mrow, ch);
                ldsm_x4(ahi[mi], a + OFF_A_HI);
                ldsm_x4(alo[mi], a + OFF_A_LO);
            }
            // B fragments: processed in two halves (2 n16 groups at a time)
            // to cap register liveness; each group still loaded exactly once.
#pragma unroll
            for (int h = 0; h < 2; ++h) {
                uint32_t bhi[2][4], blo[2][4];
#pragma unroll
                for (int p = 0; p < 2; ++p) {
                    int ng = h * 2 + p;
                    int nrow = wn * 64 + ng * 16 + ((lane >> 4) << 3) + (lane & 7);
                    int ch   = ks * 2 + ((lane >> 3) & 1);
                    uint32_t a = sb + buf + sw_off(nrow, ch);
                    ldsm_x4(bhi[p], a + OFF_B_HI);
                    ldsm_x4(blo[p], a + OFF_B_LO);
                }
                // 48 MMAs for this half, grouped by term (RAW distance 16)
#pragma unroll
                for (int mi = 0; mi < 4; ++mi)
#pragma unroll
                    for (int nl = 0; nl < 4; ++nl)
                        mma16816(acc[mi][h * 4 + nl], ahi[mi], &bhi[nl >> 1][(nl & 1) * 2]);
#pragma unroll
                for (int mi = 0; mi < 4; ++mi)
#pragma unroll
                    for (int nl = 0; nl < 4; ++nl)
                        mma16816(acc[mi][h * 4 + nl], ahi[mi], &blo[nl >> 1][(nl & 1) * 2]);
#pragma unroll
                for (int mi = 0; mi < 4; ++mi)
#pragma unroll
                    for (int nl = 0; nl < 4; ++nl)
                        mma16816(acc[mi][h * 4 + nl], alo[mi], &bhi[nl >> 1][(nl & 1) * 2]);
            }
        }

        if (pf) {
            CP_WAIT0();
            __syncthreads();
        }
    }

    // ---- epilogue: acc -> global with bias ----
#pragma unroll
    for (int ni = 0; ni < 8; ++ni) {
        int col = n0 + wn * 64 + ni * 8 + ((lane & 3) << 1);
        float b0 = g_bias[col];
        float b1 = g_bias[col + 1];
#pragma unroll
        for (int mi = 0; mi < 4; ++mi) {
            int row0 = m0 + wm * 64 + mi * 16 + (lane >> 2);
            float2 v0 = make_float2(acc[mi][ni][0] + b0, acc[mi][ni][1] + b1);
            float2 v1 = make_float2(acc[mi][ni][2] + b0, acc[mi][ni][3] + b1);
            *reinterpret_cast<float2*>(out + (size_t)row0 * OUT_F + col) = v0;
            *reinterpret_cast<float2*>(out + (size_t)(row0 + 8) * OUT_F + col) = v1;
        }
    }
}

// ============================================================================
// kernel_launch: 2 graph-capturable kernel launches, no sync, no alloc.
// Inputs (metadata order): x, weight_coef, bias_coef, P_w, P_b. Output fp32.
// ============================================================================
extern "C" void kernel_launch(void* const* d_in, const int* in_sizes, int n_in,
                              void* d_out, int out_size) {
    const float* x  = (const float*)d_in[0];
    const float* wc = (const float*)d_in[1];
    const float* bc = (const float*)d_in[2];
    const float* Pw = (const float*)d_in[3];
    const float* Pb = (const float*)d_in[4];
    float* out = (float*)d_out;

    (void)in_sizes; (void)n_in; (void)out_size;

    cudaFuncSetAttribute(gemm_kernel,
                         cudaFuncAttributeMaxDynamicSharedMemorySize, GEMM_SMEM);

    // Stage 1: fused prep (x split + W materialize + bias), DRAM bound ~650MB
    prep_kernel<<<XB + WB + OUT_F / 256, 256>>>(x, wc, bc, Pw, Pb);

    // Stage 2: y = x @ W^T + b via split-bf16 mma.sync (3 MMAs per k16 step)
    // Grid: 128 M-tiles x 4 N-tiles; same-m-tile blocks adjacent for x L2 reuse.
    gemm_kernel<<<(M_ROWS / 128) * (OUT_F / 256), 256, GEMM_SMEM>>>(out);
}

// round 9
// speedup vs baseline: 1.0760x; 1.0611x over previous
#include <cuda_runtime.h>
#include <cuda_bf16.h>
#include <cstdint>

// ============================================================================
// Problem constants
// ============================================================================
#define IN_F   1024
#define OUT_F  1024
#define INT_DIM 128
#define M_ROWS 16384              // 8 * 2048
#define WN (OUT_F * IN_F)         // 1048576
#define XN (M_ROWS * IN_F)        // 16777216

// Device-global scratch (allocation-free rule: __device__ globals are allowed)
__device__ __nv_bfloat16 g_W_hi[WN];   // W split high half, [OUT_F][IN_F] K-major
__device__ __nv_bfloat16 g_W_lo[WN];   // W split low  half
__device__ __nv_bfloat16 g_x_hi[XN];   // x split high half, [M_ROWS][IN_F]
__device__ __nv_bfloat16 g_x_lo[XN];   // x split low  half
__device__ float         g_bias[OUT_F];

__device__ __forceinline__ uint32_t smem_u32(const void* p) {
    uint32_t a;
    asm("{ .reg .u64 t; cvta.to.shared.u64 t, %1; cvt.u32.u64 %0, t; }"
        : "=r"(a) : "l"(p));
    return a;
}

__device__ __forceinline__ unsigned pack2(__nv_bfloat16 a, __nv_bfloat16 b) {
    return (unsigned)__bfloat16_as_ushort(a) | ((unsigned)__bfloat16_as_ushort(b) << 16);
}

// split a float4 into bf16 hi / lo packed uint2's
__device__ __forceinline__ void split4(float4 v, uint2& hi, uint2& lo) {
    __nv_bfloat16 h0 = __float2bfloat16(v.x), h1 = __float2bfloat16(v.y);
    __nv_bfloat16 h2 = __float2bfloat16(v.z), h3 = __float2bfloat16(v.w);
    __nv_bfloat16 l0 = __float2bfloat16(v.x - __bfloat162float(h0));
    __nv_bfloat16 l1 = __float2bfloat16(v.y - __bfloat162float(h1));
    __nv_bfloat16 l2 = __float2bfloat16(v.z - __bfloat162float(h2));
    __nv_bfloat16 l3 = __float2bfloat16(v.w - __bfloat162float(h3));
    hi = make_uint2(pack2(h0, h1), pack2(h2, h3));
    lo = make_uint2(pack2(l0, l1), pack2(l2, l3));
}

// ============================================================================
// Stage 1 (fused prep): one kernel, blockIdx-partitioned.
//   blocks [0, 16384)          : split x  -> g_x_hi / g_x_lo   (64MB rd, 64MB wr)
//   blocks [16384, 17408)      : W = coef @ P_w, split bf16    (512MB rd, 4MB wr)
//   blocks [17408, 17412)      : bias = bias_coef @ P_b
// All streaming, DRAM bound (~650 MB -> ~113 us measured, near HBM ceiling).
// ============================================================================
#define XB (XN / (256 * 4))        // 16384 blocks for x split
#define WB (WN / (256 * 4))        // 1024 blocks for W materialize

__global__ void __launch_bounds__(256)
prep_kernel(const float* __restrict__ x,  const float* __restrict__ wc,
            const float* __restrict__ bc, const float* __restrict__ Pw,
            const float* __restrict__ Pb) {
    int bx = blockIdx.x;
    int tid = threadIdx.x;

    if (bx < XB) {
        // ---- split x into bf16 hi/lo ----
        size_t pos = ((size_t)bx * 256 + tid) * 4;
        float4 v = *reinterpret_cast<const float4*>(x + pos);
        uint2 hi, lo;
        split4(v, hi, lo);
        *reinterpret_cast<uint2*>(g_x_hi + pos) = hi;
        *reinterpret_cast<uint2*>(g_x_lo + pos) = lo;
    } else if (bx < XB + WB) {
        // ---- materialize W ----
        __shared__ float c[INT_DIM];
        if (tid < INT_DIM) c[tid] = wc[tid];
        __syncthreads();
        size_t pos = ((size_t)(bx - XB) * 256 + tid) * 4;
        float4 acc = make_float4(0.f, 0.f, 0.f, 0.f);
#pragma unroll 8
        for (int d = 0; d < INT_DIM; d++) {
            float4 p = *reinterpret_cast<const float4*>(Pw + (size_t)d * WN + pos);
            float cd = c[d];
            acc.x = fmaf(cd, p.x, acc.x);
            acc.y = fmaf(cd, p.y, acc.y);
            acc.z = fmaf(cd, p.z, acc.z);
            acc.w = fmaf(cd, p.w, acc.w);
        }
        uint2 hi, lo;
        split4(acc, hi, lo);
        *reinterpret_cast<uint2*>(g_W_hi + pos) = hi;
        *reinterpret_cast<uint2*>(g_W_lo + pos) = lo;
    } else {
        // ---- materialize bias ----
        __shared__ float c[INT_DIM];
        if (tid < INT_DIM) c[tid] = bc[tid];
        __syncthreads();
        int o = (bx - XB - WB) * 256 + tid;
        float acc = 0.f;
#pragma unroll 8
        for (int d = 0; d < INT_DIM; d++)
            acc = fmaf(c[d], Pb[(size_t)d * OUT_F + o], acc);
        g_bias[o] = acc;
    }
}

// ============================================================================
// Stage 2: split-bf16 GEMM via mma.sync.m16n8k16.
//   acc += xhi*Whi + xhi*Wlo + xlo*Whi   (lo*lo dropped, ~5e-6 rel)
//
// Round-6 geometry (proven: 172 regs, no spill, tensor 72%): CTA 128x128,
// 8 warps 2(M) x 4(N), warp tile 64x32, K-chunk 64.
// NEW: 3-stage cp.async pipeline (stage 64 KB, 192 KB total). Loads run TWO
// chunks ahead; wait_group 1 only requires the chunk committed a full
// iteration ago -> barrier exposes warp skew only, not L2 latency.
// 16B chunk ch of row r stored at ch ^ (r & 7) -> conflict-free ldmatrix.
// ============================================================================
#define SM_STAGE 65536
#define OFF_A_HI 0
#define OFF_A_LO 16384
#define OFF_B_HI 32768
#define OFF_B_LO 49152
#define GEMM_SMEM (3 * SM_STAGE)
#define NKC 16   // 1024 / 64

__device__ __forceinline__ void ldsm_x4(uint32_t* r, uint32_t addr) {
    asm volatile("ldmatrix.sync.aligned.m8n8.x4.shared.b16 {%0,%1,%2,%3}, [%4];"
                 : "=r"(r[0]), "=r"(r[1]), "=r"(r[2]), "=r"(r[3]) : "r"(addr));
}
__device__ __forceinline__ void mma16816(float* d, const uint32_t* a, const uint32_t* b) {
    asm volatile(
        "mma.sync.aligned.m16n8k16.row.col.f32.bf16.bf16.f32 "
        "{%0,%1,%2,%3}, {%4,%5,%6,%7}, {%8,%9}, {%0,%1,%2,%3};"
        : "+f"(d[0]), "+f"(d[1]), "+f"(d[2]), "+f"(d[3])
        : "r"(a[0]), "r"(a[1]), "r"(a[2]), "r"(a[3]), "r"(b[0]), "r"(b[1]));
}
__device__ __forceinline__ void cp_async16(uint32_t dst, const void* src) {
    asm volatile("cp.async.cg.shared.global [%0], [%1], 16;"
                 :: "r"(dst), "l"(src) : "memory");
}
#define CP_COMMIT() asm volatile("cp.async.commit_group;" ::: "memory")
#define CP_WAIT0()  asm volatile("cp.async.wait_group 0;" ::: "memory")
#define CP_WAIT1()  asm volatile("cp.async.wait_group 1;" ::: "memory")

// swizzled byte offset inside one [128 x 128B] tile
__device__ __forceinline__ uint32_t sw_off(int row, int ch16) {
    return (uint32_t)(row * 128 + ((ch16 ^ (row & 7)) << 4));
}

__global__ void __launch_bounds__(256, 1)
gemm_kernel(float* __restrict__ out) {
    extern __shared__ char smem[];
    uint32_t sb = smem_u32(smem);
    int tid  = threadIdx.x;
    int wid  = tid >> 5;
    int lane = tid & 31;
    int wm   = wid >> 2;          // 0..1, 64-row half
    int wn   = wid & 3;           // 0..3, 32-col quarter
    // Consecutive blocks share the same x m-tile -> L2 reuse of x.
    int m0 = (int)(blockIdx.x >> 3) * 128;
    int n0 = (int)(blockIdx.x & 7) * 128;

    const __nv_bfloat16* ahp = g_x_hi + (size_t)m0 * IN_F;
    const __nv_bfloat16* alp = g_x_lo + (size_t)m0 * IN_F;
    const __nv_bfloat16* bhp = g_W_hi + (size_t)n0 * IN_F;
    const __nv_bfloat16* blp = g_W_lo + (size_t)n0 * IN_F;

    // cp.async geometry: each half-tile = 128 rows x 8 x 16B chunks = 1024
    // slots, 4 per thread: e = tid + j*256 -> row = e>>3, ch = e&7
    int tr[4], tch[4];
#pragma unroll
    for (int j = 0; j < 4; ++j) { int e = tid + j * 256; tr[j] = e >> 3; tch[j] = e & 7; }

    float acc[4][4][4];
#pragma unroll
    for (int mi = 0; mi < 4; ++mi)
#pragma unroll
        for (int ni = 0; ni < 4; ++ni)
#pragma unroll
            for (int q = 0; q < 4; ++q) acc[mi][ni][q] = 0.f;

    // helper lambda-free chunk loader (macro to keep regs flat)
#define LOAD_CHUNK(kc, stage_off) do {                                         \
        int _k = (kc) * 64;                                                    \
        uint32_t _s = sb + (stage_off);                                        \
        _Pragma("unroll")                                                      \
        for (int j = 0; j < 4; ++j) {                                          \
            uint32_t d = sw_off(tr[j], tch[j]);                                \
            size_t g = (size_t)tr[j] * IN_F + _k + tch[j] * 8;                 \
            cp_async16(_s + OFF_A_HI + d, ahp + g);                            \
            cp_async16(_s + OFF_A_LO + d, alp + g);                            \
            cp_async16(_s + OFF_B_HI + d, bhp + g);                            \
            cp_async16(_s + OFF_B_LO + d, blp + g);                            \
        }                                                                      \
        CP_COMMIT();                                                           \
    } while (0)

    // ---- prologue: preload chunks 0 and 1 into stages 0 and 1 ----
    LOAD_CHUNK(0, 0);
    LOAD_CHUNK(1, SM_STAGE);
    CP_WAIT1();              // chunk 0 landed (chunk 1 may be in flight)
    __syncthreads();

    // stage offset ring: c%3 * SM_STAGE, computed incrementally
    uint32_t buf = 0;
    uint32_t lbuf = 2 * SM_STAGE;   // stage for chunk c+2 at c=0

    // ---- main loop over 16 K-chunks, 3-stage pipelined ----
    for (int c = 0; c < NKC; ++c) {
        // issue loads for chunk c+2 into the stage that held chunk c-1
        // (all warps finished computing c-1 at the previous barrier)
        if (c + 2 < NKC) LOAD_CHUNK(c + 2, lbuf);

        // ---- compute on buf: 4 k16 steps ----
#pragma unroll
        for (int ks = 0; ks < 4; ++ks) {
            // B fragments: 2 x ldmatrix.x4 per half (paired n8 groups)
            uint32_t bhi[4][2], blo[4][2];
#pragma unroll
            for (int nip = 0; nip < 2; ++nip) {
                int nrow = wn * 32 + nip * 16 + ((lane >> 4) << 3) + (lane & 7);
                int ch   = ks * 2 + ((lane >> 3) & 1);
                uint32_t a = sb + buf + sw_off(nrow, ch);
                ldsm_x4(&bhi[nip * 2][0], a + OFF_B_HI);
                ldsm_x4(&blo[nip * 2][0], a + OFF_B_LO);
            }
            // A fragments
            uint32_t ahi[4][4], alo[4][4];
#pragma unroll
            for (int mi = 0; mi < 4; ++mi) {
                int mrow = wm * 64 + mi * 16 + (lane & 15);
                int ch   = ks * 2 + (lane >> 4);
                uint32_t a = sb + buf + sw_off(mrow, ch);
                ldsm_x4(ahi[mi], a + OFF_A_HI);
                ldsm_x4(alo[mi], a + OFF_A_LO);
            }
            // 48 MMAs grouped by term: same-acc RAW chains 16 apart
#pragma unroll
            for (int mi = 0; mi < 4; ++mi)
#pragma unroll
                for (int ni = 0; ni < 4; ++ni)
                    mma16816(acc[mi][ni], ahi[mi], bhi[ni]);
#pragma unroll
            for (int mi = 0; mi < 4; ++mi)
#pragma unroll
                for (int ni = 0; ni < 4; ++ni)
                    mma16816(acc[mi][ni], ahi[mi], blo[ni]);
#pragma unroll
            for (int mi = 0; mi < 4; ++mi)
#pragma unroll
                for (int ni = 0; ni < 4; ++ni)
                    mma16816(acc[mi][ni], alo[mi], bhi[ni]);
        }

        if (c + 1 < NKC) {
            // need chunk c+1 resident; the group issued this iter (c+2) may
            // still be in flight -> wait_group 1 (or 0 when nothing issued)
            if (c + 2 < NKC) { CP_WAIT1(); } else { CP_WAIT0(); }
            __syncthreads();
            // advance ring
            buf  = (buf  == 2 * SM_STAGE) ? 0 : buf  + SM_STAGE;
            lbuf = (lbuf == 2 * SM_STAGE) ? 0 : lbuf + SM_STAGE;
        }
    }
#undef LOAD_CHUNK

    // ---- epilogue: acc -> global with bias ----
#pragma unroll
    for (int ni = 0; ni < 4; ++ni) {
        int col = n0 + wn * 32 + ni * 8 + ((lane & 3) << 1);
        float b0 = g_bias[col];
        float b1 = g_bias[col + 1];
#pragma unroll
        for (int mi = 0; mi < 4; ++mi) {
            int row0 = m0 + wm * 64 + mi * 16 + (lane >> 2);
            float2 v0 = make_float2(acc[mi][ni][0] + b0, acc[mi][ni][1] + b1);
            float2 v1 = make_float2(acc[mi][ni][2] + b0, acc[mi][ni][3] + b1);
            *reinterpret_cast<float2*>(out + (size_t)row0 * OUT_F + col) = v0;
            *reinterpret_cast<float2*>(out + (size_t)(row0 + 8) * OUT_F + col) = v1;
        }
    }
}

// ============================================================================
// kernel_launch: 2 graph-capturable kernel launches, no sync, no alloc.
// Inputs (metadata order): x, weight_coef, bias_coef, P_w, P_b. Output fp32.
// ============================================================================
extern "C" void kernel_launch(void* const* d_in, const int* in_sizes, int n_in,
                              void* d_out, int out_size) {
    const float* x  = (const float*)d_in[0];
    const float* wc = (const float*)d_in[1];
    const float* bc = (const float*)d_in[2];
    const float* Pw = (const float*)d_in[3];
    const float* Pb = (const float*)d_in[4];
    float* out = (float*)d_out;

    (void)in_sizes; (void)n_in; (void)out_size;

    cudaFuncSetAttribute(gemm_kernel,
                         cudaFuncAttributeMaxDynamicSharedMemorySize, GEMM_SMEM);

    // Stage 1: fused prep (x split + W materialize + bias), DRAM bound ~650MB
    prep_kernel<<<XB + WB + OUT_F / 256, 256>>>(x, wc, bc, Pw, Pb);

    // Stage 2: y = x @ W^T + b via split-bf16 mma.sync (3 MMAs per k16 step)
    // Grid: 128 M-tiles x 8 N-tiles; same-m-tile blocks adjacent for x L2 reuse.
    gemm_kernel<<<(M_ROWS / 128) * (OUT_F / 128), 256, GEMM_SMEM>>>(out);
}